// round 5
// baseline (speedup 1.0000x reference)
#include <cuda_runtime.h>
#include <math.h>

#define N_NODES 10000
#define N_EDGES 160000
#define RCUT 1.4415f

typedef unsigned long long u64;

__device__ __align__(16) float g_sj[(size_t)N_NODES * 384];   // phase-1 per-node features
__device__ __align__(16) float g_msg2[(size_t)N_NODES * 512]; // phase-2 per-node message

// o-major transposed weights (filled by kT each launch)
__device__ __align__(16) float g_W1t [128 * 128];  // [o][k]
__device__ __align__(16) float g_W3t [384 * 128];  // [o][k]
__device__ __align__(16) float g_Ut  [128 * 128];
__device__ __align__(16) float g_Vt  [128 * 128];
__device__ __align__(16) float g_Wu1t[128 * 256];
__device__ __align__(16) float g_Wu2t[384 * 128];
__device__ __align__(16) float g_W2t [384 * 20];   // [o][n]

__device__ __forceinline__ float silu_f(float v) { return v / (1.0f + __expf(-v)); }

__device__ __forceinline__ void red4(float* p, float a, float b, float c, float d) {
    asm volatile("red.global.add.v4.f32 [%0], {%1,%2,%3,%4};"
                 :: "l"(p), "f"(a), "f"(b), "f"(c), "f"(d) : "memory");
}

// ---- packed f32x2 helpers -------------------------------------------------
__device__ __forceinline__ u64 pk(float x, float y) {
    u64 r; asm("mov.b64 %0, {%1,%2};" : "=l"(r) : "f"(x), "f"(y)); return r;
}
__device__ __forceinline__ u64 f2fma(u64 a, u64 b, u64 c) {
    u64 d; asm("fma.rn.f32x2 %0, %1, %2, %3;" : "=l"(d) : "l"(a), "l"(b), "l"(c)); return d;
}
__device__ __forceinline__ float hsum(u64 a) {
    float lo, hi; asm("mov.b64 {%0,%1}, %2;" : "=f"(lo), "=f"(hi) : "l"(a)); return lo + hi;
}

// ---------------------------------------------------------------------------
// Kernel T: transpose weights to o-major scratch. 188K elements.
// ---------------------------------------------------------------------------
#define KT_TOTAL (16384 + 49152 + 16384 + 16384 + 32768 + 49152 + 7680)
__global__ __launch_bounds__(256) void kT(const float* __restrict__ W1,
                                          const float* __restrict__ W3,
                                          const float* __restrict__ U,
                                          const float* __restrict__ V,
                                          const float* __restrict__ Wu1,
                                          const float* __restrict__ Wu2,
                                          const float* __restrict__ W2) {
    int idx = blockIdx.x * 256 + threadIdx.x;
    if (idx >= KT_TOTAL) return;
    if (idx < 16384) { int o = idx >> 7, k = idx & 127; g_W1t[idx] = W1[k * 128 + o]; return; }
    idx -= 16384;
    if (idx < 49152) { int o = idx >> 7, k = idx & 127; g_W3t[idx] = W3[k * 384 + o]; return; }
    idx -= 49152;
    if (idx < 16384) { int o = idx >> 7, k = idx & 127; g_Ut[idx] = U[k * 128 + o]; return; }
    idx -= 16384;
    if (idx < 16384) { int o = idx >> 7, k = idx & 127; g_Vt[idx] = V[k * 128 + o]; return; }
    idx -= 16384;
    if (idx < 32768) { int o = idx >> 8, k = idx & 255; g_Wu1t[idx] = Wu1[k * 128 + o]; return; }
    idx -= 32768;
    if (idx < 49152) { int o = idx >> 7, k = idx & 127; g_Wu2t[idx] = Wu2[k * 384 + o]; return; }
    idx -= 49152;
    { int o = idx / 20, n = idx % 20; g_W2t[idx] = W2[n * 384 + o]; }
}

// ---------------------------------------------------------------------------
// Kernel A: per-node  g_sj = silu(x[:,384:] @ W1 + b1) @ W3 + b3
// 16 nodes/block, 256 threads (2 groups x 128). f32x2 + transposed weights.
// ---------------------------------------------------------------------------
__global__ __launch_bounds__(256) void kA(const float* __restrict__ x,
                                          const float* __restrict__ b1,
                                          const float* __restrict__ b3) {
    __shared__ __align__(16) float s_in[16][128];
    __shared__ __align__(16) float t[16][128];
    const int tid = threadIdx.x;
    const int nb  = blockIdx.x * 16;

    for (int idx = tid; idx < 16 * 32; idx += 256) {
        int m = idx >> 5, c = (idx & 31) * 4;
        *(float4*)&s_in[m][c] = *(const float4*)(x + (size_t)(nb + m) * 512 + 384 + c);
    }
    __syncthreads();

    const int g = tid >> 7;      // 0..1 (8 nodes each)
    const int o = tid & 127;     // output column

    // GEMM1: t = silu(s_in @ W1 + b1)
    {
        u64 acc[8];
        u64 init = pk(b1[o], 0.0f);
#pragma unroll
        for (int j = 0; j < 8; j++) acc[j] = init;
#pragma unroll 2
        for (int k = 0; k < 128; k += 4) {
            float4 w = *(const float4*)&g_W1t[o * 128 + k];
            u64 wp0 = pk(w.x, w.y), wp1 = pk(w.z, w.w);
#pragma unroll
            for (int j = 0; j < 8; j++) {
                float4 s = *(const float4*)&s_in[g * 8 + j][k];
                acc[j] = f2fma(pk(s.x, s.y), wp0, acc[j]);
                acc[j] = f2fma(pk(s.z, s.w), wp1, acc[j]);
            }
        }
#pragma unroll
        for (int j = 0; j < 8; j++) t[g * 8 + j][o] = silu_f(hsum(acc[j]));
    }
    __syncthreads();

    // GEMM2: sj = t @ W3 + b3  (three column slabs per thread)
    {
        u64 a2[8][3];
#pragma unroll
        for (int p = 0; p < 3; p++) {
            u64 init = pk(b3[o + 128 * p], 0.0f);
#pragma unroll
            for (int j = 0; j < 8; j++) a2[j][p] = init;
        }
#pragma unroll 2
        for (int k = 0; k < 128; k += 4) {
            u64 wp[3][2];
#pragma unroll
            for (int p = 0; p < 3; p++) {
                float4 w = *(const float4*)&g_W3t[(o + 128 * p) * 128 + k];
                wp[p][0] = pk(w.x, w.y);
                wp[p][1] = pk(w.z, w.w);
            }
#pragma unroll
            for (int j = 0; j < 8; j++) {
                float4 tv = *(const float4*)&t[g * 8 + j][k];
                u64 t01 = pk(tv.x, tv.y), t23 = pk(tv.z, tv.w);
#pragma unroll
                for (int p = 0; p < 3; p++) {
                    a2[j][p] = f2fma(t01, wp[p][0], a2[j][p]);
                    a2[j][p] = f2fma(t23, wp[p][1], a2[j][p]);
                }
            }
        }
#pragma unroll
        for (int j = 0; j < 8; j++) {
            size_t base = (size_t)(nb + g * 8 + j) * 384;
#pragma unroll
            for (int p = 0; p < 3; p++) g_sj[base + o + 128 * p] = hsum(a2[j][p]);
        }
    }
}

// ---------------------------------------------------------------------------
// Kernel B: per-edge phase-1 message + scatter.
// 20 edges/block, 256 threads. W2 slice cached via 15 LDG.128 (transposed W2).
// ---------------------------------------------------------------------------
__global__ __launch_bounds__(256) void kB(const float* __restrict__ x,
                                          const int* __restrict__ ei,
                                          const float* __restrict__ ea1,
                                          const float* __restrict__ ea2,
                                          const float* __restrict__ b2,
                                          float* __restrict__ out) {
    __shared__ __align__(16) float split[20][384];   // 30 KB
    __shared__ __align__(8)  float rbfc[20][20];
    __shared__ float ea[20][3];
    __shared__ int   srcs[20], dsts[20];

    const int tid = threadIdx.x;
    const int e0  = blockIdx.x * 20;

    if (tid < 20) {
        srcs[tid] = ei[e0 + tid];
        dsts[tid] = ei[N_EDGES + e0 + tid];
    }
    if (tid >= 32 && tid < 92) {
        int q = tid - 32;
        int e = q / 3, k = q % 3;
        ea[e][k] = ea1[(size_t)(e0 + e) * 3 + k];
    }
    for (int q = tid; q < 400; q += 256) {
        int e = q / 20, n = q % 20;
        float r  = ea2[e0 + e];
        float rb = sqrtf(2.0f / RCUT) * sinpif((float)(n + 1) * r / RCUT) / r;
        float co = 0.5f * (cospif(r / RCUT) + 1.0f) * (r < RCUT ? 1.0f : 0.0f);
        rbfc[e][n] = rb * co;
    }

    const int g = tid >> 7;
    const int o = tid & 127;

    // Packed register-cached W2 slices (o-major): 5 LDG.128 per slab
    u64 w2p0[10], w2p1[10], w2p2[10];
#pragma unroll
    for (int i = 0; i < 5; i++) {
        float4 a = *(const float4*)&g_W2t[o * 20 + 4 * i];
        w2p0[2 * i] = pk(a.x, a.y); w2p0[2 * i + 1] = pk(a.z, a.w);
        float4 b = *(const float4*)&g_W2t[(o + 128) * 20 + 4 * i];
        w2p1[2 * i] = pk(b.x, b.y); w2p1[2 * i + 1] = pk(b.z, b.w);
        float4 c = *(const float4*)&g_W2t[(o + 256) * 20 + 4 * i];
        w2p2[2 * i] = pk(c.x, c.y); w2p2[2 * i + 1] = pk(c.z, c.w);
    }
    const u64 b2p0 = pk(b2[o], 0.0f);
    const u64 b2p1 = pk(b2[o + 128], 0.0f);
    const u64 b2p2 = pk(b2[o + 256], 0.0f);
    __syncthreads();

    // Pass 1: split = s_j[src] * (rbfc @ W2 + b2)
#pragma unroll
    for (int el = 0; el < 10; el++) {
        int e = g * 10 + el;
        u64 a0 = b2p0, a1 = b2p1, a2v = b2p2;
#pragma unroll
        for (int n = 0; n < 10; n++) {
            float2 rp = *(const float2*)&rbfc[e][2 * n];
            u64 r = pk(rp.x, rp.y);
            a0  = f2fma(r, w2p0[n], a0);
            a1  = f2fma(r, w2p1[n], a1);
            a2v = f2fma(r, w2p2[n], a2v);
        }
        const float* sjr = g_sj + (size_t)srcs[e] * 384;
        split[e][o]       = hsum(a0)  * sjr[o];
        split[e][o + 128] = hsum(a1)  * sjr[o + 128];
        split[e][o + 256] = hsum(a2v) * sjr[o + 256];
    }
    __syncthreads();

    // Pass 2: msg[3i+k] = x[src,3i+k]*s1[i] + s3[i]*ea1[k]; msg[384+i] = s2[i]
#pragma unroll
    for (int el = 0; el < 10; el++) {
        int e   = g * 10 + el;
        int src = srcs[e], dst = dsts[e];
        float v0, v1, v2, v3;
        if (o < 96) {
            int j0 = 4 * o;
            const float4 xv = *(const float4*)(x + (size_t)src * 512 + j0);
            float xs[4] = {xv.x, xv.y, xv.z, xv.w};
            float vals[4];
#pragma unroll
            for (int tq = 0; tq < 4; tq++) {
                int j = j0 + tq;
                int i = j / 3;
                int k = j - 3 * i;
                vals[tq] = xs[tq] * split[e][i] + split[e][256 + i] * ea[e][k];
            }
            v0 = vals[0]; v1 = vals[1]; v2 = vals[2]; v3 = vals[3];
        } else {
            int i0 = 4 * (o - 96);
            v0 = split[e][128 + i0];
            v1 = split[e][128 + i0 + 1];
            v2 = split[e][128 + i0 + 2];
            v3 = split[e][128 + i0 + 3];
        }
        red4(out + (size_t)dst * 512 + 4 * o, v0, v1, v2, v3);
    }
}

// ---------------------------------------------------------------------------
// Kernel C: per-node phase-2 message into g_msg2. 8 nodes/block, 256 threads.
// ---------------------------------------------------------------------------
__global__ __launch_bounds__(256) void kC(const float* __restrict__ xmid,
                                          const float* __restrict__ bu1,
                                          const float* __restrict__ bu2) {
    __shared__ __align__(16) float vA[8][384];   // v, later overwritten by vV
    __shared__ __align__(16) float vUs[8][384];  // v @ U
    __shared__ __align__(16) float ns[8][256];   // [norm | s]
    __shared__ __align__(16) float h1[8][128];
    __shared__ __align__(16) float h[8][384];

    const int tid = threadIdx.x;
    const int nb  = blockIdx.x * 8;

    for (int idx = tid; idx < 8 * 96; idx += 256) {
        int m = idx / 96, j = (idx % 96) * 4;
        *(float4*)&vA[m][j] = *(const float4*)(xmid + (size_t)(nb + m) * 512 + j);
    }
    for (int idx = tid; idx < 8 * 32; idx += 256) {
        int m = idx >> 5, i = (idx & 31) * 4;
        *(float4*)&ns[m][128 + i] = *(const float4*)(xmid + (size_t)(nb + m) * 512 + 384 + i);
    }
    __syncthreads();

    const int g = tid >> 7;   // 0..1 (4 nodes each)
    const int o = tid & 127;

    // vU = v @ U   (v[a,k] = vA[m][a*128+k])
    {
        u64 acc[4][3];
#pragma unroll
        for (int j = 0; j < 4; j++)
#pragma unroll
            for (int a = 0; a < 3; a++) acc[j][a] = 0ULL;
#pragma unroll 2
        for (int k = 0; k < 128; k += 4) {
            float4 w = *(const float4*)&g_Ut[o * 128 + k];
            u64 wp0 = pk(w.x, w.y), wp1 = pk(w.z, w.w);
#pragma unroll
            for (int j = 0; j < 4; j++) {
                int m = g * 4 + j;
#pragma unroll
                for (int a = 0; a < 3; a++) {
                    float4 s = *(const float4*)&vA[m][a * 128 + k];
                    acc[j][a] = f2fma(pk(s.x, s.y), wp0, acc[j][a]);
                    acc[j][a] = f2fma(pk(s.z, s.w), wp1, acc[j][a]);
                }
            }
        }
#pragma unroll
        for (int j = 0; j < 4; j++)
#pragma unroll
            for (int a = 0; a < 3; a++) vUs[g * 4 + j][a * 128 + o] = hsum(acc[j][a]);
    }
    __syncthreads();

    // vV = vU @ V  -> overwrite vA
    {
        u64 acc[4][3];
#pragma unroll
        for (int j = 0; j < 4; j++)
#pragma unroll
            for (int a = 0; a < 3; a++) acc[j][a] = 0ULL;
#pragma unroll 2
        for (int k = 0; k < 128; k += 4) {
            float4 w = *(const float4*)&g_Vt[o * 128 + k];
            u64 wp0 = pk(w.x, w.y), wp1 = pk(w.z, w.w);
#pragma unroll
            for (int j = 0; j < 4; j++) {
                int m = g * 4 + j;
#pragma unroll
                for (int a = 0; a < 3; a++) {
                    float4 s = *(const float4*)&vUs[m][a * 128 + k];
                    acc[j][a] = f2fma(pk(s.x, s.y), wp0, acc[j][a]);
                    acc[j][a] = f2fma(pk(s.z, s.w), wp1, acc[j][a]);
                }
            }
        }
        __syncthreads();
#pragma unroll
        for (int j = 0; j < 4; j++)
#pragma unroll
            for (int a = 0; a < 3; a++) vA[g * 4 + j][a * 128 + o] = hsum(acc[j][a]);
    }
    __syncthreads();

    // norms
    for (int idx = tid; idx < 8 * 128; idx += 256) {
        int m = idx >> 7, i = idx & 127;
        float x0 = vA[m][3 * i], x1 = vA[m][3 * i + 1], x2 = vA[m][3 * i + 2];
        ns[m][i] = sqrtf(x0 * x0 + x1 * x1 + x2 * x2);
    }
    __syncthreads();

    // h1 = silu([norm|s] @ Wu1 + bu1)
    {
        u64 acc[4];
        u64 init = pk(bu1[o], 0.0f);
#pragma unroll
        for (int j = 0; j < 4; j++) acc[j] = init;
#pragma unroll 2
        for (int k = 0; k < 256; k += 4) {
            float4 w = *(const float4*)&g_Wu1t[o * 256 + k];
            u64 wp0 = pk(w.x, w.y), wp1 = pk(w.z, w.w);
#pragma unroll
            for (int j = 0; j < 4; j++) {
                float4 s = *(const float4*)&ns[g * 4 + j][k];
                acc[j] = f2fma(pk(s.x, s.y), wp0, acc[j]);
                acc[j] = f2fma(pk(s.z, s.w), wp1, acc[j]);
            }
        }
#pragma unroll
        for (int j = 0; j < 4; j++) h1[g * 4 + j][o] = silu_f(hsum(acc[j]));
    }
    __syncthreads();

    // h = h1 @ Wu2 + bu2
    {
        u64 acc[4][3];
#pragma unroll
        for (int p = 0; p < 3; p++) {
            u64 init = pk(bu2[o + 128 * p], 0.0f);
#pragma unroll
            for (int j = 0; j < 4; j++) acc[j][p] = init;
        }
#pragma unroll 2
        for (int k = 0; k < 128; k += 4) {
            u64 wp[3][2];
#pragma unroll
            for (int p = 0; p < 3; p++) {
                float4 w = *(const float4*)&g_Wu2t[(o + 128 * p) * 128 + k];
                wp[p][0] = pk(w.x, w.y);
                wp[p][1] = pk(w.z, w.w);
            }
#pragma unroll
            for (int j = 0; j < 4; j++) {
                float4 tv = *(const float4*)&h1[g * 4 + j][k];
                u64 t01 = pk(tv.x, tv.y), t23 = pk(tv.z, tv.w);
#pragma unroll
                for (int p = 0; p < 3; p++) {
                    acc[j][p] = f2fma(t01, wp[p][0], acc[j][p]);
                    acc[j][p] = f2fma(t23, wp[p][1], acc[j][p]);
                }
            }
        }
#pragma unroll
        for (int j = 0; j < 4; j++)
#pragma unroll
            for (int p = 0; p < 3; p++) h[g * 4 + j][o + 128 * p] = hsum(acc[j][p]);
    }
    __syncthreads();

    // msg2
    for (int idx = tid; idx < 8 * 512; idx += 256) {
        int m = idx >> 9, j = idx & 511;
        float val;
        if (j < 384) {
            val = vUs[m][j] * h[m][j / 3];
        } else {
            int i = j - 384;
            float d = vUs[m][3 * i]     * vA[m][3 * i]
                    + vUs[m][3 * i + 1] * vA[m][3 * i + 1]
                    + vUs[m][3 * i + 2] * vA[m][3 * i + 2];
            val = d * h[m][i] + h[m][256 + i];
        }
        g_msg2[(size_t)(nb + m) * 512 + j] = val;
    }
}

// ---------------------------------------------------------------------------
// Kernel D: per-edge scatter of the per-node phase-2 message.
// ---------------------------------------------------------------------------
__global__ __launch_bounds__(256) void kD(const int* __restrict__ ei,
                                          float* __restrict__ out) {
    const int tid = threadIdx.x;
    const int g = tid >> 7, o = tid & 127;
    const int e0 = blockIdx.x * 4 + g * 2;

    const int src0 = ei[e0],     dst0 = ei[N_EDGES + e0];
    const int src1 = ei[e0 + 1], dst1 = ei[N_EDGES + e0 + 1];
    const float4 v0 = *(const float4*)(g_msg2 + (size_t)src0 * 512 + 4 * o);
    const float4 v1 = *(const float4*)(g_msg2 + (size_t)src1 * 512 + 4 * o);
    red4(out + (size_t)dst0 * 512 + 4 * o, v0.x, v0.y, v0.z, v0.w);
    red4(out + (size_t)dst1 * 512 + 4 * o, v1.x, v1.y, v1.z, v1.w);
}

// ---------------------------------------------------------------------------
extern "C" void kernel_launch(void* const* d_in, const int* in_sizes, int n_in,
                              void* d_out, int out_size) {
    const float* x   = (const float*)d_in[0];
    const int*   ei  = (const int*)d_in[1];     // int32 (jax x64 disabled)
    const float* ea1 = (const float*)d_in[2];
    const float* ea2 = (const float*)d_in[3];
    const float* W1  = (const float*)d_in[4];
    const float* b1  = (const float*)d_in[5];
    const float* W2  = (const float*)d_in[6];
    const float* b2  = (const float*)d_in[7];
    const float* W3  = (const float*)d_in[8];
    const float* b3  = (const float*)d_in[9];
    const float* U   = (const float*)d_in[10];
    const float* V   = (const float*)d_in[11];
    const float* Wu1 = (const float*)d_in[12];
    const float* bu1 = (const float*)d_in[13];
    const float* Wu2 = (const float*)d_in[14];
    const float* bu2 = (const float*)d_in[15];
    float* out = (float*)d_out;

    cudaMemcpyAsync(out, x, (size_t)N_NODES * 512 * sizeof(float),
                    cudaMemcpyDeviceToDevice);

    kT<<<(KT_TOTAL + 255) / 256, 256>>>(W1, W3, U, V, Wu1, Wu2, W2);
    kA<<<N_NODES / 16, 256>>>(x, b1, b3);
    kB<<<N_EDGES / 20, 256>>>(x, ei, ea1, ea2, b2, out);
    kC<<<N_NODES / 8, 256>>>(out, bu1, bu2);
    kD<<<N_EDGES / 4, 256>>>(ei, out);
}

// round 6
// speedup vs baseline: 1.6369x; 1.6369x over previous
#include <cuda_runtime.h>
#include <math.h>

#define N_NODES 10000
#define N_EDGES 160000
#define RCUT 1.4415f

typedef unsigned long long u64;

__device__ __align__(16) float g_sj[(size_t)N_NODES * 384];   // phase-1 per-node features
__device__ __align__(16) float g_msg2[(size_t)N_NODES * 512]; // phase-2 per-node message

// Quad-interleaved packed weights: Wq[c*(2*O) + 2*o + j] = pk(W[(4c+2j)][o], W[(4c+2j+1)][o])
// Consecutive o -> consecutive u64 pairs -> coalesced LDG.128 per (chunk, o).
__device__ __align__(16) u64 g_W1q [64 * 128];    // K=128, O=128
__device__ __align__(16) u64 g_W3q [64 * 384];    // K=128, O=384
__device__ __align__(16) u64 g_Uq  [64 * 128];
__device__ __align__(16) u64 g_Vq  [64 * 128];
__device__ __align__(16) u64 g_Wu1q[128 * 128];   // K=256, O=128
__device__ __align__(16) u64 g_Wu2q[64 * 384];    // K=128, O=384
__device__ __align__(16) u64 g_W2q [10 * 384];    // K=20,  O=384 (5 chunks)

__device__ __forceinline__ float silu_f(float v) { return v / (1.0f + __expf(-v)); }

__device__ __forceinline__ void red4(float* p, float a, float b, float c, float d) {
    asm volatile("red.global.add.v4.f32 [%0], {%1,%2,%3,%4};"
                 :: "l"(p), "f"(a), "f"(b), "f"(c), "f"(d) : "memory");
}

// ---- packed f32x2 helpers -------------------------------------------------
__device__ __forceinline__ u64 pk(float x, float y) {
    u64 r; asm("mov.b64 %0, {%1,%2};" : "=l"(r) : "f"(x), "f"(y)); return r;
}
__device__ __forceinline__ u64 f2fma(u64 a, u64 b, u64 c) {
    u64 d; asm("fma.rn.f32x2 %0, %1, %2, %3;" : "=l"(d) : "l"(a), "l"(b), "l"(c)); return d;
}
__device__ __forceinline__ float hsum(u64 a) {
    float lo, hi; asm("mov.b64 {%0,%1}, %2;" : "=f"(lo), "=f"(hi) : "l"(a)); return lo + hi;
}

// ---------------------------------------------------------------------------
// Kernel T: pack weights into quad-interleaved u64 layout. 93952 u64 total.
// ---------------------------------------------------------------------------
__device__ __forceinline__ void packq(u64* dst, const float* W, int O, int idx) {
    // idx in [0, (K/2)*O); c = idx/(2O), o = (idx%(2O))>>1, j = idx&1
    int c = idx / (2 * O);
    int rem = idx - c * 2 * O;
    int o = rem >> 1, j = rem & 1;
    int k0 = 4 * c + 2 * j;
    dst[idx] = pk(W[(size_t)k0 * O + o], W[(size_t)(k0 + 1) * O + o]);
}
#define KT_TOTAL (8192 + 24576 + 8192 + 8192 + 16384 + 24576 + 3840)
__global__ __launch_bounds__(256) void kT(const float* __restrict__ W1,
                                          const float* __restrict__ W3,
                                          const float* __restrict__ U,
                                          const float* __restrict__ V,
                                          const float* __restrict__ Wu1,
                                          const float* __restrict__ Wu2,
                                          const float* __restrict__ W2) {
    int idx = blockIdx.x * 256 + threadIdx.x;
    if (idx >= KT_TOTAL) return;
    if (idx < 8192)  { packq(g_W1q,  W1,  128, idx); return; }  idx -= 8192;
    if (idx < 24576) { packq(g_W3q,  W3,  384, idx); return; }  idx -= 24576;
    if (idx < 8192)  { packq(g_Uq,   U,   128, idx); return; }  idx -= 8192;
    if (idx < 8192)  { packq(g_Vq,   V,   128, idx); return; }  idx -= 8192;
    if (idx < 16384) { packq(g_Wu1q, Wu1, 128, idx); return; }  idx -= 16384;
    if (idx < 24576) { packq(g_Wu2q, Wu2, 384, idx); return; }  idx -= 24576;
    packq(g_W2q, W2, 384, idx);
}

// ---------------------------------------------------------------------------
// Kernel A: per-node  g_sj = silu(x[:,384:] @ W1 + b1) @ W3 + b3
// 16 nodes/block, 256 threads (2 groups x 128).
// ---------------------------------------------------------------------------
__global__ __launch_bounds__(256) void kA(const float* __restrict__ x,
                                          const float* __restrict__ b1,
                                          const float* __restrict__ b3) {
    __shared__ __align__(16) float s_in[16][128];
    __shared__ __align__(16) float t[16][128];
    const int tid = threadIdx.x;
    const int nb  = blockIdx.x * 16;

    for (int idx = tid; idx < 16 * 32; idx += 256) {
        int m = idx >> 5, c = (idx & 31) * 4;
        *(float4*)&s_in[m][c] = *(const float4*)(x + (size_t)(nb + m) * 512 + 384 + c);
    }
    __syncthreads();

    const int g = tid >> 7;      // 0..1 (8 nodes each)
    const int o = tid & 127;     // output column

    // GEMM1: t = silu(s_in @ W1 + b1)
    {
        u64 acc[8];
        u64 init = pk(b1[o], 0.0f);
#pragma unroll
        for (int j = 0; j < 8; j++) acc[j] = init;
#pragma unroll 2
        for (int k = 0; k < 128; k += 4) {
            ulonglong2 w = *(const ulonglong2*)&g_W1q[(k >> 2) * 256 + 2 * o];
#pragma unroll
            for (int j = 0; j < 8; j++) {
                float4 s = *(const float4*)&s_in[g * 8 + j][k];
                acc[j] = f2fma(pk(s.x, s.y), w.x, acc[j]);
                acc[j] = f2fma(pk(s.z, s.w), w.y, acc[j]);
            }
        }
#pragma unroll
        for (int j = 0; j < 8; j++) t[g * 8 + j][o] = silu_f(hsum(acc[j]));
    }
    __syncthreads();

    // GEMM2: sj = t @ W3 + b3  (three column slabs per thread)
    {
        u64 a2[8][3];
#pragma unroll
        for (int p = 0; p < 3; p++) {
            u64 init = pk(b3[o + 128 * p], 0.0f);
#pragma unroll
            for (int j = 0; j < 8; j++) a2[j][p] = init;
        }
#pragma unroll 2
        for (int k = 0; k < 128; k += 4) {
            ulonglong2 wp[3];
#pragma unroll
            for (int p = 0; p < 3; p++)
                wp[p] = *(const ulonglong2*)&g_W3q[(k >> 2) * 768 + 2 * (o + 128 * p)];
#pragma unroll
            for (int j = 0; j < 8; j++) {
                float4 tv = *(const float4*)&t[g * 8 + j][k];
                u64 t01 = pk(tv.x, tv.y), t23 = pk(tv.z, tv.w);
#pragma unroll
                for (int p = 0; p < 3; p++) {
                    a2[j][p] = f2fma(t01, wp[p].x, a2[j][p]);
                    a2[j][p] = f2fma(t23, wp[p].y, a2[j][p]);
                }
            }
        }
#pragma unroll
        for (int j = 0; j < 8; j++) {
            size_t base = (size_t)(nb + g * 8 + j) * 384;
#pragma unroll
            for (int p = 0; p < 3; p++) g_sj[base + o + 128 * p] = hsum(a2[j][p]);
        }
    }
}

// ---------------------------------------------------------------------------
// Kernel B: per-edge phase-1 message + scatter.
// 20 edges/block, 256 threads. W2 cached via 15 coalesced LDG.128.
// ---------------------------------------------------------------------------
__global__ __launch_bounds__(256) void kB(const float* __restrict__ x,
                                          const int* __restrict__ ei,
                                          const float* __restrict__ ea1,
                                          const float* __restrict__ ea2,
                                          const float* __restrict__ b2,
                                          float* __restrict__ out) {
    __shared__ __align__(16) float split[20][384];   // 30 KB
    __shared__ __align__(8)  float rbfc[20][20];
    __shared__ float ea[20][3];
    __shared__ int   srcs[20], dsts[20];

    const int tid = threadIdx.x;
    const int e0  = blockIdx.x * 20;

    if (tid < 20) {
        srcs[tid] = ei[e0 + tid];
        dsts[tid] = ei[N_EDGES + e0 + tid];
    }
    if (tid >= 32 && tid < 92) {
        int q = tid - 32;
        int e = q / 3, k = q % 3;
        ea[e][k] = ea1[(size_t)(e0 + e) * 3 + k];
    }
    for (int q = tid; q < 400; q += 256) {
        int e = q / 20, n = q % 20;
        float r  = ea2[e0 + e];
        float rb = sqrtf(2.0f / RCUT) * sinpif((float)(n + 1) * r / RCUT) / r;
        float co = 0.5f * (cospif(r / RCUT) + 1.0f) * (r < RCUT ? 1.0f : 0.0f);
        rbfc[e][n] = rb * co;
    }

    const int g = tid >> 7;
    const int o = tid & 127;

    // Register-cached packed W2 slices: 5 LDG.128 per slab, coalesced.
    u64 w2p0[10], w2p1[10], w2p2[10];
#pragma unroll
    for (int c = 0; c < 5; c++) {
        ulonglong2 a = *(const ulonglong2*)&g_W2q[c * 768 + 2 * o];
        w2p0[2 * c] = a.x; w2p0[2 * c + 1] = a.y;
        ulonglong2 b = *(const ulonglong2*)&g_W2q[c * 768 + 2 * (o + 128)];
        w2p1[2 * c] = b.x; w2p1[2 * c + 1] = b.y;
        ulonglong2 cc = *(const ulonglong2*)&g_W2q[c * 768 + 2 * (o + 256)];
        w2p2[2 * c] = cc.x; w2p2[2 * c + 1] = cc.y;
    }
    const u64 b2p0 = pk(b2[o], 0.0f);
    const u64 b2p1 = pk(b2[o + 128], 0.0f);
    const u64 b2p2 = pk(b2[o + 256], 0.0f);
    __syncthreads();

    // Pass 1: split = s_j[src] * (rbfc @ W2 + b2)
#pragma unroll
    for (int el = 0; el < 10; el++) {
        int e = g * 10 + el;
        u64 a0 = b2p0, a1 = b2p1, a2v = b2p2;
#pragma unroll
        for (int n = 0; n < 10; n++) {
            float2 rp = *(const float2*)&rbfc[e][2 * n];
            u64 r = pk(rp.x, rp.y);
            a0  = f2fma(r, w2p0[n], a0);
            a1  = f2fma(r, w2p1[n], a1);
            a2v = f2fma(r, w2p2[n], a2v);
        }
        const float* sjr = g_sj + (size_t)srcs[e] * 384;
        split[e][o]       = hsum(a0)  * sjr[o];
        split[e][o + 128] = hsum(a1)  * sjr[o + 128];
        split[e][o + 256] = hsum(a2v) * sjr[o + 256];
    }
    __syncthreads();

    // Pass 2: msg[3i+k] = x[src,3i+k]*s1[i] + s3[i]*ea1[k]; msg[384+i] = s2[i]
#pragma unroll
    for (int el = 0; el < 10; el++) {
        int e   = g * 10 + el;
        int src = srcs[e], dst = dsts[e];
        float v0, v1, v2, v3;
        if (o < 96) {
            int j0 = 4 * o;
            const float4 xv = *(const float4*)(x + (size_t)src * 512 + j0);
            float xs[4] = {xv.x, xv.y, xv.z, xv.w};
            float vals[4];
#pragma unroll
            for (int tq = 0; tq < 4; tq++) {
                int j = j0 + tq;
                int i = j / 3;
                int k = j - 3 * i;
                vals[tq] = xs[tq] * split[e][i] + split[e][256 + i] * ea[e][k];
            }
            v0 = vals[0]; v1 = vals[1]; v2 = vals[2]; v3 = vals[3];
        } else {
            int i0 = 4 * (o - 96);
            v0 = split[e][128 + i0];
            v1 = split[e][128 + i0 + 1];
            v2 = split[e][128 + i0 + 2];
            v3 = split[e][128 + i0 + 3];
        }
        red4(out + (size_t)dst * 512 + 4 * o, v0, v1, v2, v3);
    }
}

// ---------------------------------------------------------------------------
// Kernel C: per-node phase-2 message into g_msg2. 8 nodes/block, 256 threads.
// ---------------------------------------------------------------------------
__global__ __launch_bounds__(256) void kC(const float* __restrict__ xmid,
                                          const float* __restrict__ bu1,
                                          const float* __restrict__ bu2) {
    __shared__ __align__(16) float vA[8][384];   // v, later overwritten by vV
    __shared__ __align__(16) float vUs[8][384];  // v @ U
    __shared__ __align__(16) float ns[8][256];   // [norm | s]
    __shared__ __align__(16) float h1[8][128];
    __shared__ __align__(16) float h[8][384];

    const int tid = threadIdx.x;
    const int nb  = blockIdx.x * 8;

    for (int idx = tid; idx < 8 * 96; idx += 256) {
        int m = idx / 96, j = (idx % 96) * 4;
        *(float4*)&vA[m][j] = *(const float4*)(xmid + (size_t)(nb + m) * 512 + j);
    }
    for (int idx = tid; idx < 8 * 32; idx += 256) {
        int m = idx >> 5, i = (idx & 31) * 4;
        *(float4*)&ns[m][128 + i] = *(const float4*)(xmid + (size_t)(nb + m) * 512 + 384 + i);
    }
    __syncthreads();

    const int g = tid >> 7;   // 0..1 (4 nodes each)
    const int o = tid & 127;

    // vU = v @ U   (v[a,k] = vA[m][a*128+k])
    {
        u64 acc[4][3];
#pragma unroll
        for (int j = 0; j < 4; j++)
#pragma unroll
            for (int a = 0; a < 3; a++) acc[j][a] = 0ULL;
#pragma unroll 2
        for (int k = 0; k < 128; k += 4) {
            ulonglong2 w = *(const ulonglong2*)&g_Uq[(k >> 2) * 256 + 2 * o];
#pragma unroll
            for (int j = 0; j < 4; j++) {
                int m = g * 4 + j;
#pragma unroll
                for (int a = 0; a < 3; a++) {
                    float4 s = *(const float4*)&vA[m][a * 128 + k];
                    acc[j][a] = f2fma(pk(s.x, s.y), w.x, acc[j][a]);
                    acc[j][a] = f2fma(pk(s.z, s.w), w.y, acc[j][a]);
                }
            }
        }
#pragma unroll
        for (int j = 0; j < 4; j++)
#pragma unroll
            for (int a = 0; a < 3; a++) vUs[g * 4 + j][a * 128 + o] = hsum(acc[j][a]);
    }
    __syncthreads();

    // vV = vU @ V  -> overwrite vA
    {
        u64 acc[4][3];
#pragma unroll
        for (int j = 0; j < 4; j++)
#pragma unroll
            for (int a = 0; a < 3; a++) acc[j][a] = 0ULL;
#pragma unroll 2
        for (int k = 0; k < 128; k += 4) {
            ulonglong2 w = *(const ulonglong2*)&g_Vq[(k >> 2) * 256 + 2 * o];
#pragma unroll
            for (int j = 0; j < 4; j++) {
                int m = g * 4 + j;
#pragma unroll
                for (int a = 0; a < 3; a++) {
                    float4 s = *(const float4*)&vUs[m][a * 128 + k];
                    acc[j][a] = f2fma(pk(s.x, s.y), w.x, acc[j][a]);
                    acc[j][a] = f2fma(pk(s.z, s.w), w.y, acc[j][a]);
                }
            }
        }
        __syncthreads();
#pragma unroll
        for (int j = 0; j < 4; j++)
#pragma unroll
            for (int a = 0; a < 3; a++) vA[g * 4 + j][a * 128 + o] = hsum(acc[j][a]);
    }
    __syncthreads();

    // norms
    for (int idx = tid; idx < 8 * 128; idx += 256) {
        int m = idx >> 7, i = idx & 127;
        float x0 = vA[m][3 * i], x1 = vA[m][3 * i + 1], x2 = vA[m][3 * i + 2];
        ns[m][i] = sqrtf(x0 * x0 + x1 * x1 + x2 * x2);
    }
    __syncthreads();

    // h1 = silu([norm|s] @ Wu1 + bu1)
    {
        u64 acc[4];
        u64 init = pk(bu1[o], 0.0f);
#pragma unroll
        for (int j = 0; j < 4; j++) acc[j] = init;
#pragma unroll 2
        for (int k = 0; k < 256; k += 4) {
            ulonglong2 w = *(const ulonglong2*)&g_Wu1q[(k >> 2) * 256 + 2 * o];
#pragma unroll
            for (int j = 0; j < 4; j++) {
                float4 s = *(const float4*)&ns[g * 4 + j][k];
                acc[j] = f2fma(pk(s.x, s.y), w.x, acc[j]);
                acc[j] = f2fma(pk(s.z, s.w), w.y, acc[j]);
            }
        }
#pragma unroll
        for (int j = 0; j < 4; j++) h1[g * 4 + j][o] = silu_f(hsum(acc[j]));
    }
    __syncthreads();

    // h = h1 @ Wu2 + bu2
    {
        u64 acc[4][3];
#pragma unroll
        for (int p = 0; p < 3; p++) {
            u64 init = pk(bu2[o + 128 * p], 0.0f);
#pragma unroll
            for (int j = 0; j < 4; j++) acc[j][p] = init;
        }
#pragma unroll 2
        for (int k = 0; k < 128; k += 4) {
            ulonglong2 wp[3];
#pragma unroll
            for (int p = 0; p < 3; p++)
                wp[p] = *(const ulonglong2*)&g_Wu2q[(k >> 2) * 768 + 2 * (o + 128 * p)];
#pragma unroll
            for (int j = 0; j < 4; j++) {
                float4 tv = *(const float4*)&h1[g * 4 + j][k];
                u64 t01 = pk(tv.x, tv.y), t23 = pk(tv.z, tv.w);
#pragma unroll
                for (int p = 0; p < 3; p++) {
                    acc[j][p] = f2fma(t01, wp[p].x, acc[j][p]);
                    acc[j][p] = f2fma(t23, wp[p].y, acc[j][p]);
                }
            }
        }
#pragma unroll
        for (int j = 0; j < 4; j++)
#pragma unroll
            for (int p = 0; p < 3; p++) h[g * 4 + j][o + 128 * p] = hsum(acc[j][p]);
    }
    __syncthreads();

    // msg2
    for (int idx = tid; idx < 8 * 512; idx += 256) {
        int m = idx >> 9, j = idx & 511;
        float val;
        if (j < 384) {
            val = vUs[m][j] * h[m][j / 3];
        } else {
            int i = j - 384;
            float d = vUs[m][3 * i]     * vA[m][3 * i]
                    + vUs[m][3 * i + 1] * vA[m][3 * i + 1]
                    + vUs[m][3 * i + 2] * vA[m][3 * i + 2];
            val = d * h[m][i] + h[m][256 + i];
        }
        g_msg2[(size_t)(nb + m) * 512 + j] = val;
    }
}

// ---------------------------------------------------------------------------
// Kernel D: per-edge scatter of the per-node phase-2 message.
// ---------------------------------------------------------------------------
__global__ __launch_bounds__(256) void kD(const int* __restrict__ ei,
                                          float* __restrict__ out) {
    const int tid = threadIdx.x;
    const int g = tid >> 7, o = tid & 127;
    const int e0 = blockIdx.x * 4 + g * 2;

    const int src0 = ei[e0],     dst0 = ei[N_EDGES + e0];
    const int src1 = ei[e0 + 1], dst1 = ei[N_EDGES + e0 + 1];
    const float4 v0 = *(const float4*)(g_msg2 + (size_t)src0 * 512 + 4 * o);
    const float4 v1 = *(const float4*)(g_msg2 + (size_t)src1 * 512 + 4 * o);
    red4(out + (size_t)dst0 * 512 + 4 * o, v0.x, v0.y, v0.z, v0.w);
    red4(out + (size_t)dst1 * 512 + 4 * o, v1.x, v1.y, v1.z, v1.w);
}

// ---------------------------------------------------------------------------
extern "C" void kernel_launch(void* const* d_in, const int* in_sizes, int n_in,
                              void* d_out, int out_size) {
    const float* x   = (const float*)d_in[0];
    const int*   ei  = (const int*)d_in[1];     // int32 (jax x64 disabled)
    const float* ea1 = (const float*)d_in[2];
    const float* ea2 = (const float*)d_in[3];
    const float* W1  = (const float*)d_in[4];
    const float* b1  = (const float*)d_in[5];
    const float* W2  = (const float*)d_in[6];
    const float* b2  = (const float*)d_in[7];
    const float* W3  = (const float*)d_in[8];
    const float* b3  = (const float*)d_in[9];
    const float* U   = (const float*)d_in[10];
    const float* V   = (const float*)d_in[11];
    const float* Wu1 = (const float*)d_in[12];
    const float* bu1 = (const float*)d_in[13];
    const float* Wu2 = (const float*)d_in[14];
    const float* bu2 = (const float*)d_in[15];
    float* out = (float*)d_out;

    cudaMemcpyAsync(out, x, (size_t)N_NODES * 512 * sizeof(float),
                    cudaMemcpyDeviceToDevice);

    kT<<<(KT_TOTAL + 255) / 256, 256>>>(W1, W3, U, V, Wu1, Wu2, W2);
    kA<<<N_NODES / 16, 256>>>(x, b1, b3);
    kB<<<N_EDGES / 20, 256>>>(x, ei, ea1, ea2, b2, out);
    kC<<<N_NODES / 8, 256>>>(out, bu1, bu2);
    kD<<<N_EDGES / 4, 256>>>(ei, out);
}